// round 13
// baseline (speedup 1.0000x reference)
#include <cuda_runtime.h>
#include <cuda_bf16.h>
#include <math.h>
#include <stdint.h>

#define BB 16
#define CIN 128
#define COUT 128
#define HH 64
#define WW 64
#define ATT 16
#define KN 4
#define BN_EPS 1e-5f

// ---------------------------------------------------------------------------
// scratch (device globals; no allocation allowed)
// ---------------------------------------------------------------------------
__device__ float g_pooled[BB * CIN];
__device__ float g_coef[BB * KN * 9];
__device__ float g_ch[BB * CIN];
__device__ float g_fl[BB * COUT];
__device__ float g_spa[BB * 9];
// agg filters pre-split to bf16: layout [b][tap][o(128)][i(128)]
__device__ __align__(128) __nv_bfloat16 g_ah[(size_t)BB * 9 * 128 * 128];
__device__ __align__(128) __nv_bfloat16 g_al[(size_t)BB * 9 * 128 * 128];
// x pre-split, NCHW, packed u32 = {bf16 hi <<16 | bf16 lo} per element
__device__ __align__(128) uint32_t g_xs[(size_t)BB * CIN * HH * WW];

// ---------------------------------------------------------------------------
// asm helpers
// ---------------------------------------------------------------------------
__device__ __forceinline__ uint32_t smem_u32(const void* p) {
    uint32_t a;
    asm("{ .reg .u64 t; cvta.to.shared.u64 t, %1; cvt.u32.u64 %0, t; }" : "=r"(a) : "l"(p));
    return a;
}
__device__ __forceinline__ void cp_async16(uint32_t dst, const void* src) {
    asm volatile("cp.async.cg.shared.global [%0], [%1], 16;"
                 :: "r"(dst), "l"(src) : "memory");
}
__device__ __forceinline__ void cp_async4(uint32_t dst, const void* src, int szb) {
    asm volatile("cp.async.ca.shared.global [%0], [%1], 4, %2;"
                 :: "r"(dst), "l"(src), "r"(szb) : "memory");
}
__device__ __forceinline__ void ldsm_x4(uint32_t* r, uint32_t a) {
    asm volatile("ldmatrix.sync.aligned.m8n8.x4.shared.b16 {%0,%1,%2,%3}, [%4];"
                 : "=r"(r[0]), "=r"(r[1]), "=r"(r[2]), "=r"(r[3]) : "r"(a));
}
__device__ __forceinline__ void ldsm_x2(uint32_t* r, uint32_t a) {
    asm volatile("ldmatrix.sync.aligned.m8n8.x2.shared.b16 {%0,%1}, [%2];"
                 : "=r"(r[0]), "=r"(r[1]) : "r"(a));
}
__device__ __forceinline__ void mma16816(float* c, const uint32_t* a, const uint32_t* b) {
    asm volatile(
        "mma.sync.aligned.m16n8k16.row.col.f32.bf16.bf16.f32 "
        "{%0,%1,%2,%3}, {%4,%5,%6,%7}, {%8,%9}, {%0,%1,%2,%3};"
        : "+f"(c[0]), "+f"(c[1]), "+f"(c[2]), "+f"(c[3])
        : "r"(a[0]), "r"(a[1]), "r"(a[2]), "r"(a[3]), "r"(b[0]), "r"(b[1]));
}
__device__ __forceinline__ uint32_t pack_hilo(float v) {
    __nv_bfloat16 h = __float2bfloat16(v);
    float hf = __bfloat162float(h);
    __nv_bfloat16 l = __float2bfloat16(v - hf);
    return ((uint32_t)__bfloat16_as_ushort(h) << 16) | (uint32_t)__bfloat16_as_ushort(l);
}

// ---------------- kernel 1: fused x hi/lo split + global average pool ------
__global__ void __launch_bounds__(256) xsplit_pool_kernel(const float* __restrict__ x) {
    const int bi = blockIdx.x;
    const float4* xp = (const float4*)(x + (size_t)bi * HH * WW);
    uint4* xo = (uint4*)(g_xs + (size_t)bi * HH * WW);
    float s = 0.f;
    for (int t = threadIdx.x; t < HH * WW / 4; t += 256) {
        float4 v = xp[t];
        uint4 o;
        o.x = pack_hilo(v.x);
        o.y = pack_hilo(v.y);
        o.z = pack_hilo(v.z);
        o.w = pack_hilo(v.w);
        xo[t] = o;
        s += v.x + v.y + v.z + v.w;
    }
#pragma unroll
    for (int o2 = 16; o2; o2 >>= 1) s += __shfl_down_sync(0xffffffff, s, o2);
    __shared__ float ws[8];
    if ((threadIdx.x & 31) == 0) ws[threadIdx.x >> 5] = s;
    __syncthreads();
    if (threadIdx.x == 0) {
        float t = 0.f;
#pragma unroll
        for (int k = 0; k < 8; k++) t += ws[k];
        g_pooled[bi] = t * (1.0f / (HH * WW));
    }
}

// ---------------- kernel 2: attention trunk + branches (1 block) -----------
__global__ void attn_kernel(
    const float* __restrict__ fc_w,
    const float* __restrict__ bn_gamma, const float* __restrict__ bn_beta,
    const float* __restrict__ bn_mean, const float* __restrict__ bn_var,
    const float* __restrict__ ch_w, const float* __restrict__ ch_b,
    const float* __restrict__ flt_w, const float* __restrict__ flt_b,
    const float* __restrict__ spa_w, const float* __restrict__ spa_b,
    const float* __restrict__ fld_w, const float* __restrict__ fld_b,
    const float* __restrict__ ker_w, const float* __restrict__ ker_b) {
    __shared__ float sp[BB][CIN];
    __shared__ float sh[BB][ATT];
    __shared__ float sfld[BB][9];
    __shared__ float sker[BB][KN];
    int tid = threadIdx.x;
    for (int t = tid; t < BB * CIN; t += 256) sp[t / CIN][t % CIN] = g_pooled[t];
    __syncthreads();
    {
        int b = tid / ATT, a = tid % ATT;
        float s = 0.f;
#pragma unroll 16
        for (int i = 0; i < CIN; i++) s += sp[b][i] * fc_w[a * CIN + i];
        float inv = rsqrtf(bn_var[a] + BN_EPS);
        s = (s - bn_mean[a]) * (bn_gamma[a] * inv) + bn_beta[a];
        sh[b][a] = fmaxf(s, 0.f);
    }
    __syncthreads();
    for (int t = tid; t < BB * CIN; t += 256) {
        int b = t / CIN, i = t % CIN;
        float s = ch_b[i];
#pragma unroll
        for (int a = 0; a < ATT; a++) s += sh[b][a] * ch_w[i * ATT + a];
        g_ch[t] = 1.f / (1.f + expf(-s));
    }
    for (int t = tid; t < BB * COUT; t += 256) {
        int b = t / COUT, o = t % COUT;
        float s = flt_b[o];
#pragma unroll
        for (int a = 0; a < ATT; a++) s += sh[b][a] * flt_w[o * ATT + a];
        g_fl[t] = 1.f / (1.f + expf(-s));
    }
    for (int t = tid; t < BB * 9; t += 256) {
        int b = t / 9, j = t % 9;
        float s = spa_b[j];
#pragma unroll
        for (int a = 0; a < ATT; a++) s += sh[b][a] * spa_w[j * ATT + a];
        g_spa[t] = 1.f / (1.f + expf(-s));
        float s2 = fld_b[j];
#pragma unroll
        for (int a = 0; a < ATT; a++) s2 += sh[b][a] * fld_w[j * ATT + a];
        sfld[b][j] = 1.f / (1.f + expf(-s2));
    }
    if (tid < BB * KN) {
        int b = tid / KN, n = tid % KN;
        float s = ker_b[n];
#pragma unroll
        for (int a = 0; a < ATT; a++) s += sh[b][a] * ker_w[n * ATT + a];
        sker[b][n] = s;
    }
    __syncthreads();
    if (tid < BB) {
        int b = tid;
        float m = -1e30f;
#pragma unroll
        for (int n = 0; n < KN; n++) m = fmaxf(m, sker[b][n]);
        float e[KN], sum = 0.f;
#pragma unroll
        for (int n = 0; n < KN; n++) { e[n] = expf(sker[b][n] - m); sum += e[n]; }
#pragma unroll
        for (int n = 0; n < KN; n++) sker[b][n] = e[n] / sum;
    }
    __syncthreads();
    for (int t = tid; t < BB * KN * 9; t += 256) {
        int b = t / (KN * 9), n = (t / 9) % KN, j = t % 9;
        g_coef[t] = sker[b][n] * sfld[b][j];
    }
}

// ---------------- kernel 3: aggregation -> bf16 hi/lo filter tiles ---------
// (R8 verbatim) grid (64, 9): blockIdx.y owns ONE pq.
__global__ void __launch_bounds__(256) agg_kernel(const float* __restrict__ weight) {
    __shared__ float scoef[BB * KN * 9];
    __shared__ float sch[BB * CIN];
    __shared__ float sfl[BB * COUT];
    __shared__ float sspa[BB * 9];
    for (int t = threadIdx.x; t < BB * KN * 9; t += 256) scoef[t] = g_coef[t];
    for (int t = threadIdx.x; t < BB * CIN; t += 256) sch[t] = g_ch[t];
    for (int t = threadIdx.x; t < BB * COUT; t += 256) sfl[t] = g_fl[t];
    for (int t = threadIdx.x; t < BB * 9; t += 256) sspa[t] = g_spa[t];
    __syncthreads();
    const int oi = blockIdx.x * 256 + threadIdx.x;   // 0..16383
    const int o = oi >> 7, i = oi & 127;
    const int pq = blockIdx.y;
    const size_t nstride = (size_t)COUT * CIN * 81;
    const float* wbase = weight + (size_t)oi * 81 + pq * 9;
    float w[KN * 9];
#pragma unroll
    for (int n = 0; n < KN; n++)
#pragma unroll
        for (int uv = 0; uv < 9; uv++)
            w[n * 9 + uv] = __ldg(wbase + n * nstride + uv);
#pragma unroll 1
    for (int bg = 0; bg < 4; bg++) {
        const int b0 = bg * 4;
        float acc[4] = {0.f, 0.f, 0.f, 0.f};
#pragma unroll
        for (int k = 0; k < KN * 9; k++) {
            float wv = w[k];
#pragma unroll
            for (int bb = 0; bb < 4; bb++)
                acc[bb] += wv * scoef[(b0 + bb) * (KN * 9) + k];
        }
#pragma unroll
        for (int bb = 0; bb < 4; bb++) {
            int b = b0 + bb;
            float s = acc[bb] * sch[b * CIN + i] * sfl[b * COUT + o] * sspa[b * 9 + pq];
            __nv_bfloat16 h = __float2bfloat16(s);
            __nv_bfloat16 l = __float2bfloat16(s - __bfloat162float(h));
            size_t oidx = (((size_t)b * 9 + pq) * 128 + o) * 128 + i;
            g_ah[oidx] = h;
            g_al[oidx] = l;
        }
    }
}

// ---------------- kernel 4: pipelined implicit-GEMM conv (bf16 hi/lo) ------
// R12 conv + zero-register software pipeline:
//  - B fetch for chunk c+1 = 16x 4B cp.async into packed staging [n][k]
//    (144B pitch), issued before MMA(c). A fetch double-buffered likewise.
//  - hi/lo split moves to a short smem->smem phase (LDS.128 + PRMT + STS.128).
// smem layout (dynamic, 96KB):
//  A buf0: Ah 0..10240, Al 10240..20480 ; A buf1: 20480..40960
//  Bh 40960..51200 ; Bl 51200..61440
//  staging0 61440..79872 ; staging1 79872..98304 (128 rows x 144B)
#define APITCH 80
#define SPITCH 144
#define SM_B 40960u
#define SM_ST 61440u
#define SM_TOTAL 98304

__global__ void __launch_bounds__(256, 2) conv_mma_kernel(float* __restrict__ out) {
    extern __shared__ __align__(16) char sm[];
    const uint32_t sbase = smem_u32(sm);
    const uint32_t sBh = sbase + SM_B;
    const uint32_t sBl = sbase + SM_B + 10240u;

    const int tid = threadIdx.x;
    const int wid = tid >> 5;
    const int lid = tid & 31;
    const int b = blockIdx.y;
    const int y0 = blockIdx.x * 2;

    const int mbase = (wid >> 2) * 64;
    const int nbase = (wid & 3) * 32;

    float acc[4][4][4];
#pragma unroll
    for (int mt = 0; mt < 4; mt++)
#pragma unroll
        for (int nt = 0; nt < 4; nt++)
#pragma unroll
            for (int r = 0; r < 4; r++) acc[mt][nt][r] = 0.f;

    const uint32_t* xsb = g_xs + (size_t)b * CIN * HH * WW;
    const __nv_bfloat16* gAh = g_ah + (size_t)b * 9 * 128 * 128;
    const __nv_bfloat16* gAl = g_al + (size_t)b * 9 * 128 * 128;

    // copy-phase thread mappings
    const int bn = tid & 127;
    const int ihalf = tid >> 7;
    const int brp = bn >> 6;
    const int bpx = bn & 63;
    const int ao = tid >> 1;
    const int au = tid & 1;

    // ldmatrix lane mapping (validated R8)
    const int r8 = lid & 7;
    const int g1 = (lid >> 3) & 1;
    const int g2 = lid >> 4;
    const uint32_t aoff = (uint32_t)((mbase + g1 * 8 + r8) * APITCH + g2 * 16);
    const uint32_t boff = (uint32_t)((nbase + r8) * APITCH + g1 * 16);

    // issue cp.async group for chunk c into buffers [c&1]
    auto issue_copy = [&](int c) {
        const int tap = c >> 2, kc = c & 3, ic0 = kc * 32;
        const int buf = c & 1;
        // A: 4x 16B per thread
        {
            const size_t ab = ((size_t)tap * 128 + ao) * 128 + ic0 + au * 16;
            const uint32_t dst = sbase + (uint32_t)(buf * 20480) +
                                 (uint32_t)(ao * APITCH + au * 32);
            cp_async16(dst, gAh + ab);
            cp_async16(dst + 16, gAh + ab + 8);
            cp_async16(dst + 10240u, gAl + ab);
            cp_async16(dst + 10240u + 16, gAl + ab + 8);
        }
        // B: 16x 4B per thread into packed staging [bn][k]
        {
            const int p = tap / 3 - 1, q = tap % 3 - 1;
            const int gy = y0 + brp + p, gx = bpx + q;
            const bool inb = (gx >= 0) && (gx < WW) && (gy >= 0) && (gy < HH);
            const int szb = inb ? 4 : 0;
            const uint32_t* src = xsb + (inb ? (gy * WW + gx) : 0) +
                                  (size_t)(ic0 + ihalf * 16) * (HH * WW);
            const uint32_t dst = sbase + SM_ST + (uint32_t)(buf * 18432) +
                                 (uint32_t)(bn * SPITCH + ihalf * 64);
#pragma unroll
            for (int kk = 0; kk < 16; kk++)
                cp_async4(dst + kk * 4, src + (size_t)kk * (HH * WW), szb);
        }
        asm volatile("cp.async.commit_group;" ::: "memory");
    };

    // prologue: fetch chunk 0
    issue_copy(0);
    asm volatile("cp.async.wait_group 0;" ::: "memory");

    for (int c = 0; c < 36; c++) {
        const int buf = c & 1;
        __syncthreads();   // prev MMA done with B planes; staging/A arrivals visible

        // ---- split staging[buf] -> Bh/Bl planes ----
        {
            const uint32_t st = sbase + SM_ST + (uint32_t)(buf * 18432) +
                                (uint32_t)(bn * SPITCH + ihalf * 64);
            uint32_t pck[16];
#pragma unroll
            for (int j = 0; j < 4; j++) {
                uint4 v;
                asm volatile("ld.shared.v4.u32 {%0,%1,%2,%3}, [%4];"
                             : "=r"(v.x), "=r"(v.y), "=r"(v.z), "=r"(v.w)
                             : "r"(st + j * 16));
                pck[j * 4] = v.x; pck[j * 4 + 1] = v.y;
                pck[j * 4 + 2] = v.z; pck[j * 4 + 3] = v.w;
            }
            uint32_t h[8], l[8];
#pragma unroll
            for (int j = 0; j < 8; j++) {
                h[j] = __byte_perm(pck[2 * j], pck[2 * j + 1], 0x7632);
                l[j] = __byte_perm(pck[2 * j], pck[2 * j + 1], 0x5410);
            }
            char* dh = sm + SM_B + bn * APITCH + ihalf * 32;
            char* dl = sm + SM_B + 10240 + bn * APITCH + ihalf * 32;
            *(uint4*)(dh) = *(const uint4*)(h);
            *(uint4*)(dh + 16) = *(const uint4*)(h + 4);
            *(uint4*)(dl) = *(const uint4*)(l);
            *(uint4*)(dl + 16) = *(const uint4*)(l + 4);
        }
        __syncthreads();

        // ---- prefetch next chunk (fire-and-forget) ----
        if (c + 1 < 36) issue_copy(c + 1);

        // ---- MMA: B frags once per ks; A per (mt, plane) ----
        const uint32_t sAh = sbase + (uint32_t)(buf * 20480);
        const uint32_t sAl = sAh + 10240u;
#pragma unroll
        for (int ks = 0; ks < 2; ks++) {
            const uint32_t kb = (uint32_t)(ks * 32);
            uint32_t bh[4][2], bl[4][2];
#pragma unroll
            for (int nt = 0; nt < 4; nt++)
                ldsm_x2(bh[nt], sBh + boff + (uint32_t)(nt * 8 * APITCH) + kb);
#pragma unroll
            for (int nt = 0; nt < 4; nt++)
                ldsm_x2(bl[nt], sBl + boff + (uint32_t)(nt * 8 * APITCH) + kb);
#pragma unroll
            for (int mt = 0; mt < 4; mt++) {
                uint32_t ah[4];
                ldsm_x4(ah, sAh + aoff + (uint32_t)(mt * 16 * APITCH) + kb);
#pragma unroll
                for (int nt = 0; nt < 4; nt++) mma16816(acc[mt][nt], ah, bh[nt]);
#pragma unroll
                for (int nt = 0; nt < 4; nt++) mma16816(acc[mt][nt], ah, bl[nt]);
            }
#pragma unroll
            for (int mt = 0; mt < 4; mt++) {
                uint32_t al[4];
                ldsm_x4(al, sAl + aoff + (uint32_t)(mt * 16 * APITCH) + kb);
#pragma unroll
                for (int nt = 0; nt < 4; nt++) mma16816(acc[mt][nt], al, bh[nt]);
            }
        }
        asm volatile("cp.async.wait_group 0;" ::: "memory");
    }

    // ---- epilogue: direct stores (ch/fl/spa folded into agg) ----
    float* ob = out + (size_t)b * COUT * HH * WW;
#pragma unroll
    for (int mt = 0; mt < 4; mt++) {
        const int o = mbase + mt * 16 + (lid >> 2);
#pragma unroll
        for (int nt = 0; nt < 4; nt++) {
            const int nn = nbase + nt * 8 + (lid & 3) * 2;
            const int rp = nn >> 6, px = nn & 63;
            float* dst = ob + ((size_t)o * HH + (y0 + rp)) * WW + px;
            float2 v0 = make_float2(acc[mt][nt][0], acc[mt][nt][1]);
            float2 v1 = make_float2(acc[mt][nt][2], acc[mt][nt][3]);
            *(float2*)(dst) = v0;
            *(float2*)(dst + 8 * (size_t)HH * WW) = v1;
        }
    }
}

// ---------------- launch ----------------------------------------------------
extern "C" void kernel_launch(void* const* d_in, const int* in_sizes, int n_in,
                              void* d_out, int out_size) {
    const float* x        = (const float*)d_in[0];
    const float* weight   = (const float*)d_in[1];
    const float* fc_w     = (const float*)d_in[2];
    const float* bn_gamma = (const float*)d_in[3];
    const float* bn_beta  = (const float*)d_in[4];
    const float* bn_mean  = (const float*)d_in[5];
    const float* bn_var   = (const float*)d_in[6];
    const float* ch_w     = (const float*)d_in[7];
    const float* ch_b     = (const float*)d_in[8];
    const float* flt_w    = (const float*)d_in[9];
    const float* flt_b    = (const float*)d_in[10];
    const float* spa_w    = (const float*)d_in[11];
    const float* spa_b    = (const float*)d_in[12];
    const float* fld_w    = (const float*)d_in[13];
    const float* fld_b    = (const float*)d_in[14];
    const float* ker_w    = (const float*)d_in[15];
    const float* ker_b    = (const float*)d_in[16];
    float* out = (float*)d_out;

    cudaFuncSetAttribute(conv_mma_kernel,
                         cudaFuncAttributeMaxDynamicSharedMemorySize, SM_TOTAL);

    xsplit_pool_kernel<<<BB * CIN, 256>>>(x);
    attn_kernel<<<1, 256>>>(fc_w, bn_gamma, bn_beta, bn_mean, bn_var,
                            ch_w, ch_b, flt_w, flt_b, spa_w, spa_b,
                            fld_w, fld_b, ker_w, ker_b);
    agg_kernel<<<dim3(64, 9), 256>>>(weight);
    conv_mma_kernel<<<dim3(32, BB), 256, SM_TOTAL>>>(out);
}

// round 14
// speedup vs baseline: 1.1014x; 1.1014x over previous
#include <cuda_runtime.h>
#include <cuda_bf16.h>
#include <math.h>
#include <stdint.h>

#define BB 16
#define CIN 128
#define COUT 128
#define HH 64
#define WW 64
#define ATT 16
#define KN 4
#define BN_EPS 1e-5f

// ---------------------------------------------------------------------------
// scratch (device globals; no allocation allowed)
// ---------------------------------------------------------------------------
__device__ float g_pooled[BB * CIN];
__device__ float g_coef[BB * KN * 9];
__device__ float g_ch[BB * CIN];
__device__ float g_fl[BB * COUT];
__device__ float g_spa[BB * 9];
// agg filters pre-split to bf16: layout [b][tap][o(128)][i(128)]
__device__ __align__(128) __nv_bfloat16 g_ah[(size_t)BB * 9 * 128 * 128];
__device__ __align__(128) __nv_bfloat16 g_al[(size_t)BB * 9 * 128 * 128];
// x pre-split, NCHW, packed u32 = {bf16 hi <<16 | bf16 lo} per element
__device__ __align__(128) uint32_t g_xs[(size_t)BB * CIN * HH * WW];

// ---------------------------------------------------------------------------
// asm helpers
// ---------------------------------------------------------------------------
__device__ __forceinline__ uint32_t smem_u32(const void* p) {
    uint32_t a;
    asm("{ .reg .u64 t; cvta.to.shared.u64 t, %1; cvt.u32.u64 %0, t; }" : "=r"(a) : "l"(p));
    return a;
}
__device__ __forceinline__ void cp_async16(uint32_t dst, const void* src) {
    asm volatile("cp.async.cg.shared.global [%0], [%1], 16;"
                 :: "r"(dst), "l"(src) : "memory");
}
__device__ __forceinline__ void ldsm_x4(uint32_t* r, uint32_t a) {
    asm volatile("ldmatrix.sync.aligned.m8n8.x4.shared.b16 {%0,%1,%2,%3}, [%4];"
                 : "=r"(r[0]), "=r"(r[1]), "=r"(r[2]), "=r"(r[3]) : "r"(a));
}
__device__ __forceinline__ void ldsm_x2(uint32_t* r, uint32_t a) {
    asm volatile("ldmatrix.sync.aligned.m8n8.x2.shared.b16 {%0,%1}, [%2];"
                 : "=r"(r[0]), "=r"(r[1]) : "r"(a));
}
__device__ __forceinline__ void mma16816(float* c, const uint32_t* a, const uint32_t* b) {
    asm volatile(
        "mma.sync.aligned.m16n8k16.row.col.f32.bf16.bf16.f32 "
        "{%0,%1,%2,%3}, {%4,%5,%6,%7}, {%8,%9}, {%0,%1,%2,%3};"
        : "+f"(c[0]), "+f"(c[1]), "+f"(c[2]), "+f"(c[3])
        : "r"(a[0]), "r"(a[1]), "r"(a[2]), "r"(a[3]), "r"(b[0]), "r"(b[1]));
}
__device__ __forceinline__ uint32_t pack_hilo(float v) {
    __nv_bfloat16 h = __float2bfloat16(v);
    float hf = __bfloat162float(h);
    __nv_bfloat16 l = __float2bfloat16(v - hf);
    return ((uint32_t)__bfloat16_as_ushort(h) << 16) | (uint32_t)__bfloat16_as_ushort(l);
}

// ---------------- kernel 1: fused x hi/lo split + global average pool ------
__global__ void __launch_bounds__(256) xsplit_pool_kernel(const float* __restrict__ x) {
    const int bi = blockIdx.x;
    const float4* xp = (const float4*)(x + (size_t)bi * HH * WW);
    uint4* xo = (uint4*)(g_xs + (size_t)bi * HH * WW);
    float s = 0.f;
    for (int t = threadIdx.x; t < HH * WW / 4; t += 256) {
        float4 v = xp[t];
        uint4 o;
        o.x = pack_hilo(v.x);
        o.y = pack_hilo(v.y);
        o.z = pack_hilo(v.z);
        o.w = pack_hilo(v.w);
        xo[t] = o;
        s += v.x + v.y + v.z + v.w;
    }
#pragma unroll
    for (int o2 = 16; o2; o2 >>= 1) s += __shfl_down_sync(0xffffffff, s, o2);
    __shared__ float ws[8];
    if ((threadIdx.x & 31) == 0) ws[threadIdx.x >> 5] = s;
    __syncthreads();
    if (threadIdx.x == 0) {
        float t = 0.f;
#pragma unroll
        for (int k = 0; k < 8; k++) t += ws[k];
        g_pooled[bi] = t * (1.0f / (HH * WW));
    }
}

// ---------------- kernel 2: attention trunk + branches (1 block) -----------
__global__ void attn_kernel(
    const float* __restrict__ fc_w,
    const float* __restrict__ bn_gamma, const float* __restrict__ bn_beta,
    const float* __restrict__ bn_mean, const float* __restrict__ bn_var,
    const float* __restrict__ ch_w, const float* __restrict__ ch_b,
    const float* __restrict__ flt_w, const float* __restrict__ flt_b,
    const float* __restrict__ spa_w, const float* __restrict__ spa_b,
    const float* __restrict__ fld_w, const float* __restrict__ fld_b,
    const float* __restrict__ ker_w, const float* __restrict__ ker_b) {
    __shared__ float sp[BB][CIN];
    __shared__ float sh[BB][ATT];
    __shared__ float sfld[BB][9];
    __shared__ float sker[BB][KN];
    int tid = threadIdx.x;
    for (int t = tid; t < BB * CIN; t += 256) sp[t / CIN][t % CIN] = g_pooled[t];
    __syncthreads();
    {
        int b = tid / ATT, a = tid % ATT;
        float s = 0.f;
#pragma unroll 16
        for (int i = 0; i < CIN; i++) s += sp[b][i] * fc_w[a * CIN + i];
        float inv = rsqrtf(bn_var[a] + BN_EPS);
        s = (s - bn_mean[a]) * (bn_gamma[a] * inv) + bn_beta[a];
        sh[b][a] = fmaxf(s, 0.f);
    }
    __syncthreads();
    for (int t = tid; t < BB * CIN; t += 256) {
        int b = t / CIN, i = t % CIN;
        float s = ch_b[i];
#pragma unroll
        for (int a = 0; a < ATT; a++) s += sh[b][a] * ch_w[i * ATT + a];
        g_ch[t] = 1.f / (1.f + expf(-s));
    }
    for (int t = tid; t < BB * COUT; t += 256) {
        int b = t / COUT, o = t % COUT;
        float s = flt_b[o];
#pragma unroll
        for (int a = 0; a < ATT; a++) s += sh[b][a] * flt_w[o * ATT + a];
        g_fl[t] = 1.f / (1.f + expf(-s));
    }
    for (int t = tid; t < BB * 9; t += 256) {
        int b = t / 9, j = t % 9;
        float s = spa_b[j];
#pragma unroll
        for (int a = 0; a < ATT; a++) s += sh[b][a] * spa_w[j * ATT + a];
        g_spa[t] = 1.f / (1.f + expf(-s));
        float s2 = fld_b[j];
#pragma unroll
        for (int a = 0; a < ATT; a++) s2 += sh[b][a] * fld_w[j * ATT + a];
        sfld[b][j] = 1.f / (1.f + expf(-s2));
    }
    if (tid < BB * KN) {
        int b = tid / KN, n = tid % KN;
        float s = ker_b[n];
#pragma unroll
        for (int a = 0; a < ATT; a++) s += sh[b][a] * ker_w[n * ATT + a];
        sker[b][n] = s;
    }
    __syncthreads();
    if (tid < BB) {
        int b = tid;
        float m = -1e30f;
#pragma unroll
        for (int n = 0; n < KN; n++) m = fmaxf(m, sker[b][n]);
        float e[KN], sum = 0.f;
#pragma unroll
        for (int n = 0; n < KN; n++) { e[n] = expf(sker[b][n] - m); sum += e[n]; }
#pragma unroll
        for (int n = 0; n < KN; n++) sker[b][n] = e[n] / sum;
    }
    __syncthreads();
    for (int t = tid; t < BB * KN * 9; t += 256) {
        int b = t / (KN * 9), n = (t / 9) % KN, j = t % 9;
        g_coef[t] = sker[b][n] * sfld[b][j];
    }
}

// ---------------- kernel 3: aggregation -> bf16 hi/lo filter tiles ---------
// (R8 verbatim) grid (64, 9): blockIdx.y owns ONE pq.
__global__ void __launch_bounds__(256) agg_kernel(const float* __restrict__ weight) {
    __shared__ float scoef[BB * KN * 9];
    __shared__ float sch[BB * CIN];
    __shared__ float sfl[BB * COUT];
    __shared__ float sspa[BB * 9];
    for (int t = threadIdx.x; t < BB * KN * 9; t += 256) scoef[t] = g_coef[t];
    for (int t = threadIdx.x; t < BB * CIN; t += 256) sch[t] = g_ch[t];
    for (int t = threadIdx.x; t < BB * COUT; t += 256) sfl[t] = g_fl[t];
    for (int t = threadIdx.x; t < BB * 9; t += 256) sspa[t] = g_spa[t];
    __syncthreads();
    const int oi = blockIdx.x * 256 + threadIdx.x;   // 0..16383
    const int o = oi >> 7, i = oi & 127;
    const int pq = blockIdx.y;
    const size_t nstride = (size_t)COUT * CIN * 81;
    const float* wbase = weight + (size_t)oi * 81 + pq * 9;
    float w[KN * 9];
#pragma unroll
    for (int n = 0; n < KN; n++)
#pragma unroll
        for (int uv = 0; uv < 9; uv++)
            w[n * 9 + uv] = __ldg(wbase + n * nstride + uv);
#pragma unroll 1
    for (int bg = 0; bg < 4; bg++) {
        const int b0 = bg * 4;
        float acc[4] = {0.f, 0.f, 0.f, 0.f};
#pragma unroll
        for (int k = 0; k < KN * 9; k++) {
            float wv = w[k];
#pragma unroll
            for (int bb = 0; bb < 4; bb++)
                acc[bb] += wv * scoef[(b0 + bb) * (KN * 9) + k];
        }
#pragma unroll
        for (int bb = 0; bb < 4; bb++) {
            int b = b0 + bb;
            float s = acc[bb] * sch[b * CIN + i] * sfl[b * COUT + o] * sspa[b * 9 + pq];
            __nv_bfloat16 h = __float2bfloat16(s);
            __nv_bfloat16 l = __float2bfloat16(s - __bfloat162float(h));
            size_t oidx = (((size_t)b * 9 + pq) * 128 + o) * 128 + i;
            g_ah[oidx] = h;
            g_al[oidx] = l;
        }
    }
}

// ---------------- kernel 4: double-buffered implicit-GEMM conv -------------
// R12 conv + double-buffered A/B planes, ONE __syncthreads per chunk:
//   iter c: issue A(c+1) cp.async -> B-build(c+1) -> MMA(c) -> wait+sync
// Build temporaries die before MMA (no live range across it).
// smem (dynamic 80KB): bufA[j] = j*20480 (Ah|Al), bufB[j] = 40960 + j*20480.
#define APITCH 80
#define SM_TOTAL 81920

__global__ void __launch_bounds__(256, 2) conv_mma_kernel(float* __restrict__ out) {
    extern __shared__ __align__(16) char sm[];
    const uint32_t sbase = smem_u32(sm);

    const int tid = threadIdx.x;
    const int wid = tid >> 5;
    const int lid = tid & 31;
    const int b = blockIdx.y;
    const int y0 = blockIdx.x * 2;

    const int mbase = (wid >> 2) * 64;
    const int nbase = (wid & 3) * 32;

    float acc[4][4][4];
#pragma unroll
    for (int mt = 0; mt < 4; mt++)
#pragma unroll
        for (int nt = 0; nt < 4; nt++)
#pragma unroll
            for (int r = 0; r < 4; r++) acc[mt][nt][r] = 0.f;

    const uint32_t* xsb = g_xs + (size_t)b * CIN * HH * WW;
    const __nv_bfloat16* gAh = g_ah + (size_t)b * 9 * 128 * 128;
    const __nv_bfloat16* gAl = g_al + (size_t)b * 9 * 128 * 128;

    // copy-phase thread mappings (R12)
    const int bn = tid & 127;
    const int ihalf = tid >> 7;
    const int brp = bn >> 6;
    const int bpx = bn & 63;
    const int ao = tid >> 1;
    const int au = tid & 1;

    // ldmatrix lane mapping (validated R8)
    const int r8 = lid & 7;
    const int g1 = (lid >> 3) & 1;
    const int g2 = lid >> 4;
    const uint32_t aoff = (uint32_t)((mbase + g1 * 8 + r8) * APITCH + g2 * 16);
    const uint32_t boff = (uint32_t)((nbase + r8) * APITCH + g1 * 16);

    // ---- A issue for chunk c (cp.async, fire-and-forget) ----
    auto issue_a = [&](int c) {
        const int tap = c >> 2, ic0 = (c & 3) * 32;
        const size_t ab = ((size_t)tap * 128 + ao) * 128 + ic0 + au * 16;
        const uint32_t dst = sbase + (uint32_t)((c & 1) * 20480) +
                             (uint32_t)(ao * APITCH + au * 32);
        cp_async16(dst, gAh + ab);
        cp_async16(dst + 16, gAh + ab + 8);
        cp_async16(dst + 10240u, gAl + ab);
        cp_async16(dst + 10240u + 16, gAl + ab + 8);
        asm volatile("cp.async.commit_group;" ::: "memory");
    };
    // ---- B build for chunk c (LDG + byte_perm + STS; temporaries die here) --
    auto build_b = [&](int c) {
        const int tap = c >> 2, ic0 = (c & 3) * 32;
        const int p = tap / 3 - 1, q = tap % 3 - 1;
        const int gy = y0 + brp + p, gx = bpx + q;
        const bool inb = (gx >= 0) && (gx < WW) && (gy >= 0) && (gy < HH);
        const uint32_t* src = xsb + (inb ? (gy * WW + gx) : 0) +
                              (size_t)(ic0 + ihalf * 16) * (HH * WW);
        uint32_t pck[16];
#pragma unroll
        for (int kk = 0; kk < 16; kk++)
            pck[kk] = inb ? __ldg(src + (size_t)kk * (HH * WW)) : 0u;
        uint32_t h[8], l[8];
#pragma unroll
        for (int j = 0; j < 8; j++) {
            h[j] = __byte_perm(pck[2 * j], pck[2 * j + 1], 0x7632);
            l[j] = __byte_perm(pck[2 * j], pck[2 * j + 1], 0x5410);
        }
        char* base = sm + 40960 + (c & 1) * 20480 + bn * APITCH + ihalf * 32;
        *(uint4*)(base) = *(const uint4*)(h);
        *(uint4*)(base + 16) = *(const uint4*)(h + 4);
        *(uint4*)(base + 10240) = *(const uint4*)(l);
        *(uint4*)(base + 10240 + 16) = *(const uint4*)(l + 4);
    };

    // prologue: fill buffers for chunk 0
    issue_a(0);
    build_b(0);
    asm volatile("cp.async.wait_group 0;" ::: "memory");
    __syncthreads();

    for (int c = 0; c < 36; c++) {
        // prefetch next chunk into the other buffer (before MMA of this one)
        if (c + 1 < 36) {
            issue_a(c + 1);
            build_b(c + 1);
        }

        // ---- MMA(c): B frags once per ks; A per (mt, plane) ----
        const uint32_t sAh = sbase + (uint32_t)((c & 1) * 20480);
        const uint32_t sAl = sAh + 10240u;
        const uint32_t sBh = sbase + 40960u + (uint32_t)((c & 1) * 20480);
        const uint32_t sBl = sBh + 10240u;
#pragma unroll
        for (int ks = 0; ks < 2; ks++) {
            const uint32_t kb = (uint32_t)(ks * 32);
            uint32_t bh[4][2], bl[4][2];
#pragma unroll
            for (int nt = 0; nt < 4; nt++)
                ldsm_x2(bh[nt], sBh + boff + (uint32_t)(nt * 8 * APITCH) + kb);
#pragma unroll
            for (int nt = 0; nt < 4; nt++)
                ldsm_x2(bl[nt], sBl + boff + (uint32_t)(nt * 8 * APITCH) + kb);
#pragma unroll
            for (int mt = 0; mt < 4; mt++) {
                uint32_t ah[4];
                ldsm_x4(ah, sAh + aoff + (uint32_t)(mt * 16 * APITCH) + kb);
#pragma unroll
                for (int nt = 0; nt < 4; nt++) mma16816(acc[mt][nt], ah, bh[nt]);
#pragma unroll
                for (int nt = 0; nt < 4; nt++) mma16816(acc[mt][nt], ah, bl[nt]);
            }
#pragma unroll
            for (int mt = 0; mt < 4; mt++) {
                uint32_t al[4];
                ldsm_x4(al, sAl + aoff + (uint32_t)(mt * 16 * APITCH) + kb);
#pragma unroll
                for (int nt = 0; nt < 4; nt++) mma16816(acc[mt][nt], al, bh[nt]);
            }
        }
        asm volatile("cp.async.wait_group 0;" ::: "memory");
        __syncthreads();
    }

    // ---- epilogue: direct stores (ch/fl/spa folded into agg) ----
    float* ob = out + (size_t)b * COUT * HH * WW;
#pragma unroll
    for (int mt = 0; mt < 4; mt++) {
        const int o = mbase + mt * 16 + (lid >> 2);
#pragma unroll
        for (int nt = 0; nt < 4; nt++) {
            const int nn = nbase + nt * 8 + (lid & 3) * 2;
            const int rp = nn >> 6, px = nn & 63;
            float* dst = ob + ((size_t)o * HH + (y0 + rp)) * WW + px;
            float2 v0 = make_float2(acc[mt][nt][0], acc[mt][nt][1]);
            float2 v1 = make_float2(acc[mt][nt][2], acc[mt][nt][3]);
            *(float2*)(dst) = v0;
            *(float2*)(dst + 8 * (size_t)HH * WW) = v1;
        }
    }
}

// ---------------- launch ----------------------------------------------------
extern "C" void kernel_launch(void* const* d_in, const int* in_sizes, int n_in,
                              void* d_out, int out_size) {
    const float* x        = (const float*)d_in[0];
    const float* weight   = (const float*)d_in[1];
    const float* fc_w     = (const float*)d_in[2];
    const float* bn_gamma = (const float*)d_in[3];
    const float* bn_beta  = (const float*)d_in[4];
    const float* bn_mean  = (const float*)d_in[5];
    const float* bn_var   = (const float*)d_in[6];
    const float* ch_w     = (const float*)d_in[7];
    const float* ch_b     = (const float*)d_in[8];
    const float* flt_w    = (const float*)d_in[9];
    const float* flt_b    = (const float*)d_in[10];
    const float* spa_w    = (const float*)d_in[11];
    const float* spa_b    = (const float*)d_in[12];
    const float* fld_w    = (const float*)d_in[13];
    const float* fld_b    = (const float*)d_in[14];
    const float* ker_w    = (const float*)d_in[15];
    const float* ker_b    = (const float*)d_in[16];
    float* out = (float*)d_out;

    cudaFuncSetAttribute(conv_mma_kernel,
                         cudaFuncAttributeMaxDynamicSharedMemorySize, SM_TOTAL);

    xsplit_pool_kernel<<<BB * CIN, 256>>>(x);
    attn_kernel<<<1, 256>>>(fc_w, bn_gamma, bn_beta, bn_mean, bn_var,
                            ch_w, ch_b, flt_w, flt_b, spa_w, spa_b,
                            fld_w, fld_b, ker_w, ker_b);
    agg_kernel<<<dim3(64, 9), 256>>>(weight);
    conv_mma_kernel<<<dim3(32, BB), 256, SM_TOTAL>>>(out);
}

// round 15
// speedup vs baseline: 1.4163x; 1.2860x over previous
#include <cuda_runtime.h>
#include <cuda_fp16.h>
#include <math.h>
#include <stdint.h>

#define BB 16
#define CIN 128
#define COUT 128
#define HH 64
#define WW 64
#define ATT 16
#define KN 4
#define BN_EPS 1e-5f

// ---------------------------------------------------------------------------
// scratch (device globals; no allocation allowed)
// ---------------------------------------------------------------------------
__device__ float g_pooled[BB * CIN];
__device__ float g_coef[BB * KN * 9];
__device__ float g_ch[BB * CIN];
__device__ float g_fl[BB * COUT];
__device__ float g_spa[BB * 9];
// agg filters pre-split to fp16 hi/lo: layout [b][tap][o(128)][i(128)]
__device__ __align__(128) __half g_ah[(size_t)BB * 9 * 128 * 128];
__device__ __align__(128) __half g_al[(size_t)BB * 9 * 128 * 128];
// x as fp16, channel-pair packed: [b][i2(64)][pix(4096)], u32 = half2(2*i2, 2*i2+1)
__device__ __align__(128) uint32_t g_x16[(size_t)BB * 64 * HH * WW];

// ---------------------------------------------------------------------------
// asm helpers
// ---------------------------------------------------------------------------
__device__ __forceinline__ uint32_t smem_u32(const void* p) {
    uint32_t a;
    asm("{ .reg .u64 t; cvta.to.shared.u64 t, %1; cvt.u32.u64 %0, t; }" : "=r"(a) : "l"(p));
    return a;
}
__device__ __forceinline__ void cp_async16(uint32_t dst, const void* src) {
    asm volatile("cp.async.cg.shared.global [%0], [%1], 16;"
                 :: "r"(dst), "l"(src) : "memory");
}
__device__ __forceinline__ void ldsm_x4(uint32_t* r, uint32_t a) {
    asm volatile("ldmatrix.sync.aligned.m8n8.x4.shared.b16 {%0,%1,%2,%3}, [%4];"
                 : "=r"(r[0]), "=r"(r[1]), "=r"(r[2]), "=r"(r[3]) : "r"(a));
}
__device__ __forceinline__ void ldsm_x2(uint32_t* r, uint32_t a) {
    asm volatile("ldmatrix.sync.aligned.m8n8.x2.shared.b16 {%0,%1}, [%2];"
                 : "=r"(r[0]), "=r"(r[1]) : "r"(a));
}
__device__ __forceinline__ void mma16816_f16(float* c, const uint32_t* a, const uint32_t* b) {
    asm volatile(
        "mma.sync.aligned.m16n8k16.row.col.f32.f16.f16.f32 "
        "{%0,%1,%2,%3}, {%4,%5,%6,%7}, {%8,%9}, {%0,%1,%2,%3};"
        : "+f"(c[0]), "+f"(c[1]), "+f"(c[2]), "+f"(c[3])
        : "r"(a[0]), "r"(a[1]), "r"(a[2]), "r"(a[3]), "r"(b[0]), "r"(b[1]));
}

// ---------------- kernel 1: x -> fp16 pair-packed + global average pool ----
// One block per (b, i2) channel pair: 1024 blocks.
__global__ void __launch_bounds__(256) xsplit_pool_kernel(const float* __restrict__ x) {
    const int bi2 = blockIdx.x;            // b*64 + i2
    const int b = bi2 >> 6;
    const int i2 = bi2 & 63;
    const float* pa = x + ((size_t)(b * CIN + 2 * i2) * HH * WW);
    const float* pb = pa + HH * WW;
    uint4* xo = (uint4*)(g_x16 + (size_t)bi2 * HH * WW);
    float sa = 0.f, sb = 0.f;
    for (int t = threadIdx.x; t < HH * WW / 4; t += 256) {
        float4 va = ((const float4*)pa)[t];
        float4 vb = ((const float4*)pb)[t];
        sa += va.x + va.y + va.z + va.w;
        sb += vb.x + vb.y + vb.z + vb.w;
        uint4 o;
        __half2 h0 = __floats2half2_rn(va.x, vb.x);
        __half2 h1 = __floats2half2_rn(va.y, vb.y);
        __half2 h2 = __floats2half2_rn(va.z, vb.z);
        __half2 h3 = __floats2half2_rn(va.w, vb.w);
        o.x = *(uint32_t*)&h0;
        o.y = *(uint32_t*)&h1;
        o.z = *(uint32_t*)&h2;
        o.w = *(uint32_t*)&h3;
        xo[t] = o;
    }
#pragma unroll
    for (int o2 = 16; o2; o2 >>= 1) {
        sa += __shfl_down_sync(0xffffffff, sa, o2);
        sb += __shfl_down_sync(0xffffffff, sb, o2);
    }
    __shared__ float wsa[8], wsb[8];
    if ((threadIdx.x & 31) == 0) {
        wsa[threadIdx.x >> 5] = sa;
        wsb[threadIdx.x >> 5] = sb;
    }
    __syncthreads();
    if (threadIdx.x == 0) {
        float ta = 0.f, tb = 0.f;
#pragma unroll
        for (int k = 0; k < 8; k++) { ta += wsa[k]; tb += wsb[k]; }
        g_pooled[b * CIN + 2 * i2] = ta * (1.0f / (HH * WW));
        g_pooled[b * CIN + 2 * i2 + 1] = tb * (1.0f / (HH * WW));
    }
}

// ---------------- kernel 2: attention trunk + branches (1 block) -----------
__global__ void attn_kernel(
    const float* __restrict__ fc_w,
    const float* __restrict__ bn_gamma, const float* __restrict__ bn_beta,
    const float* __restrict__ bn_mean, const float* __restrict__ bn_var,
    const float* __restrict__ ch_w, const float* __restrict__ ch_b,
    const float* __restrict__ flt_w, const float* __restrict__ flt_b,
    const float* __restrict__ spa_w, const float* __restrict__ spa_b,
    const float* __restrict__ fld_w, const float* __restrict__ fld_b,
    const float* __restrict__ ker_w, const float* __restrict__ ker_b) {
    __shared__ float sp[BB][CIN];
    __shared__ float sh[BB][ATT];
    __shared__ float sfld[BB][9];
    __shared__ float sker[BB][KN];
    int tid = threadIdx.x;
    for (int t = tid; t < BB * CIN; t += 256) sp[t / CIN][t % CIN] = g_pooled[t];
    __syncthreads();
    {
        int b = tid / ATT, a = tid % ATT;
        float s = 0.f;
#pragma unroll 16
        for (int i = 0; i < CIN; i++) s += sp[b][i] * fc_w[a * CIN + i];
        float inv = rsqrtf(bn_var[a] + BN_EPS);
        s = (s - bn_mean[a]) * (bn_gamma[a] * inv) + bn_beta[a];
        sh[b][a] = fmaxf(s, 0.f);
    }
    __syncthreads();
    for (int t = tid; t < BB * CIN; t += 256) {
        int b = t / CIN, i = t % CIN;
        float s = ch_b[i];
#pragma unroll
        for (int a = 0; a < ATT; a++) s += sh[b][a] * ch_w[i * ATT + a];
        g_ch[t] = 1.f / (1.f + expf(-s));
    }
    for (int t = tid; t < BB * COUT; t += 256) {
        int b = t / COUT, o = t % COUT;
        float s = flt_b[o];
#pragma unroll
        for (int a = 0; a < ATT; a++) s += sh[b][a] * flt_w[o * ATT + a];
        g_fl[t] = 1.f / (1.f + expf(-s));
    }
    for (int t = tid; t < BB * 9; t += 256) {
        int b = t / 9, j = t % 9;
        float s = spa_b[j];
#pragma unroll
        for (int a = 0; a < ATT; a++) s += sh[b][a] * spa_w[j * ATT + a];
        g_spa[t] = 1.f / (1.f + expf(-s));
        float s2 = fld_b[j];
#pragma unroll
        for (int a = 0; a < ATT; a++) s2 += sh[b][a] * fld_w[j * ATT + a];
        sfld[b][j] = 1.f / (1.f + expf(-s2));
    }
    if (tid < BB * KN) {
        int b = tid / KN, n = tid % KN;
        float s = ker_b[n];
#pragma unroll
        for (int a = 0; a < ATT; a++) s += sh[b][a] * ker_w[n * ATT + a];
        sker[b][n] = s;
    }
    __syncthreads();
    if (tid < BB) {
        int b = tid;
        float m = -1e30f;
#pragma unroll
        for (int n = 0; n < KN; n++) m = fmaxf(m, sker[b][n]);
        float e[KN], sum = 0.f;
#pragma unroll
        for (int n = 0; n < KN; n++) { e[n] = expf(sker[b][n] - m); sum += e[n]; }
#pragma unroll
        for (int n = 0; n < KN; n++) sker[b][n] = e[n] / sum;
    }
    __syncthreads();
    for (int t = tid; t < BB * KN * 9; t += 256) {
        int b = t / (KN * 9), n = (t / 9) % KN, j = t % 9;
        g_coef[t] = sker[b][n] * sfld[b][j];
    }
}

// ---------------- kernel 3: aggregation -> fp16 hi/lo filter tiles ---------
// grid (64, 9): blockIdx.y owns ONE pq.
__global__ void __launch_bounds__(256) agg_kernel(const float* __restrict__ weight) {
    __shared__ float scoef[BB * KN * 9];
    __shared__ float sch[BB * CIN];
    __shared__ float sfl[BB * COUT];
    __shared__ float sspa[BB * 9];
    for (int t = threadIdx.x; t < BB * KN * 9; t += 256) scoef[t] = g_coef[t];
    for (int t = threadIdx.x; t < BB * CIN; t += 256) sch[t] = g_ch[t];
    for (int t = threadIdx.x; t < BB * COUT; t += 256) sfl[t] = g_fl[t];
    for (int t = threadIdx.x; t < BB * 9; t += 256) sspa[t] = g_spa[t];
    __syncthreads();
    const int oi = blockIdx.x * 256 + threadIdx.x;   // 0..16383
    const int o = oi >> 7, i = oi & 127;
    const int pq = blockIdx.y;
    const size_t nstride = (size_t)COUT * CIN * 81;
    const float* wbase = weight + (size_t)oi * 81 + pq * 9;
    float w[KN * 9];
#pragma unroll
    for (int n = 0; n < KN; n++)
#pragma unroll
        for (int uv = 0; uv < 9; uv++)
            w[n * 9 + uv] = __ldg(wbase + n * nstride + uv);
#pragma unroll 1
    for (int bg = 0; bg < 4; bg++) {
        const int b0 = bg * 4;
        float acc[4] = {0.f, 0.f, 0.f, 0.f};
#pragma unroll
        for (int k = 0; k < KN * 9; k++) {
            float wv = w[k];
#pragma unroll
            for (int bb = 0; bb < 4; bb++)
                acc[bb] += wv * scoef[(b0 + bb) * (KN * 9) + k];
        }
#pragma unroll
        for (int bb = 0; bb < 4; bb++) {
            int b = b0 + bb;
            float s = acc[bb] * sch[b * CIN + i] * sfl[b * COUT + o] * sspa[b * 9 + pq];
            __half h = __float2half_rn(s);
            __half l = __float2half_rn(s - __half2float(h));
            size_t oidx = (((size_t)b * 9 + pq) * 128 + o) * 128 + i;
            g_ah[oidx] = h;
            g_al[oidx] = l;
        }
    }
}

// ---------------- kernel 4: double-buffered implicit-GEMM conv (fp16) ------
// R14 structure (double buffer, 1 sync/chunk) with fp16 2-pass math:
//   A = fp16 hi/lo (2 planes), B = fp16 single plane.
//   MMA per chunk: 2 ks x (B frags once; Ah x16 mma, Al x16 mma) = 64 mma.
// smem (dynamic 61.5KB): bufA[j]=j*20480 (Ah|Al); bufB[j]=40960+j*10240.
#define APITCH 80
#define SM_TOTAL 61440

__global__ void __launch_bounds__(256, 2) conv_mma_kernel(float* __restrict__ out) {
    extern __shared__ __align__(16) char sm[];
    const uint32_t sbase = smem_u32(sm);

    const int tid = threadIdx.x;
    const int wid = tid >> 5;
    const int lid = tid & 31;
    const int b = blockIdx.y;
    const int y0 = blockIdx.x * 2;

    const int mbase = (wid >> 2) * 64;
    const int nbase = (wid & 3) * 32;

    float acc[4][4][4];
#pragma unroll
    for (int mt = 0; mt < 4; mt++)
#pragma unroll
        for (int nt = 0; nt < 4; nt++)
#pragma unroll
            for (int r = 0; r < 4; r++) acc[mt][nt][r] = 0.f;

    const uint32_t* xpb = g_x16 + (size_t)b * 64 * HH * WW;
    const __half* gAh = g_ah + (size_t)b * 9 * 128 * 128;
    const __half* gAl = g_al + (size_t)b * 9 * 128 * 128;

    // copy-phase thread mappings
    const int bn = tid & 127;
    const int ihalf = tid >> 7;            // 0/1 -> channel offset 0/16 in chunk
    const int brp = bn >> 6;
    const int bpx = bn & 63;
    const int ao = tid >> 1;
    const int au = tid & 1;

    // ldmatrix lane mapping (validated)
    const int r8 = lid & 7;
    const int g1 = (lid >> 3) & 1;
    const int g2 = lid >> 4;
    const uint32_t aoff = (uint32_t)((mbase + g1 * 8 + r8) * APITCH + g2 * 16);
    const uint32_t boff = (uint32_t)((nbase + r8) * APITCH + g1 * 16);

    // ---- A issue for chunk c (cp.async, fire-and-forget) ----
    auto issue_a = [&](int c) {
        const int tap = c >> 2, ic0 = (c & 3) * 32;
        const size_t ab = ((size_t)tap * 128 + ao) * 128 + ic0 + au * 16;
        const uint32_t dst = sbase + (uint32_t)((c & 1) * 20480) +
                             (uint32_t)(ao * APITCH + au * 32);
        cp_async16(dst, gAh + ab);
        cp_async16(dst + 16, gAh + ab + 8);
        cp_async16(dst + 10240u, gAl + ab);
        cp_async16(dst + 10240u + 16, gAl + ab + 8);
        asm volatile("cp.async.commit_group;" ::: "memory");
    };
    // ---- B build for chunk c: 8x LDG.32 (pair-packed fp16) + 2x STS.128 ----
    auto build_b = [&](int c) {
        const int tap = c >> 2, ic0 = (c & 3) * 32;
        const int p = tap / 3 - 1, q = tap % 3 - 1;
        const int gy = y0 + brp + p, gx = bpx + q;
        const bool inb = (gx >= 0) && (gx < WW) && (gy >= 0) && (gy < HH);
        const uint32_t* src = xpb + (inb ? (gy * WW + gx) : 0) +
                              (size_t)(ic0 / 2 + ihalf * 8) * (HH * WW);
        uint32_t v[8];
#pragma unroll
        for (int kk = 0; kk < 8; kk++)
            v[kk] = inb ? __ldg(src + (size_t)kk * (HH * WW)) : 0u;
        char* base = sm + 40960 + (c & 1) * 10240 + bn * APITCH + ihalf * 32;
        *(uint4*)(base) = *(const uint4*)(v);
        *(uint4*)(base + 16) = *(const uint4*)(v + 4);
    };

    // prologue: fill buffers for chunk 0
    issue_a(0);
    build_b(0);
    asm volatile("cp.async.wait_group 0;" ::: "memory");
    __syncthreads();

    for (int c = 0; c < 36; c++) {
        // prefetch next chunk into the other buffer (before MMA of this one)
        if (c + 1 < 36) {
            issue_a(c + 1);
            build_b(c + 1);
        }

        // ---- MMA(c): B frags once per ks; Ah then Al ----
        const uint32_t sAh = sbase + (uint32_t)((c & 1) * 20480);
        const uint32_t sAl = sAh + 10240u;
        const uint32_t sB = sbase + 40960u + (uint32_t)((c & 1) * 10240);
#pragma unroll
        for (int ks = 0; ks < 2; ks++) {
            const uint32_t kb = (uint32_t)(ks * 32);
            uint32_t bf[4][2];
#pragma unroll
            for (int nt = 0; nt < 4; nt++)
                ldsm_x2(bf[nt], sB + boff + (uint32_t)(nt * 8 * APITCH) + kb);
#pragma unroll
            for (int mt = 0; mt < 4; mt++) {
                uint32_t ah[4];
                ldsm_x4(ah, sAh + aoff + (uint32_t)(mt * 16 * APITCH) + kb);
#pragma unroll
                for (int nt = 0; nt < 4; nt++) mma16816_f16(acc[mt][nt], ah, bf[nt]);
            }
#pragma unroll
            for (int mt = 0; mt < 4; mt++) {
                uint32_t al[4];
                ldsm_x4(al, sAl + aoff + (uint32_t)(mt * 16 * APITCH) + kb);
#pragma unroll
                for (int nt = 0; nt < 4; nt++) mma16816_f16(acc[mt][nt], al, bf[nt]);
            }
        }
        asm volatile("cp.async.wait_group 0;" ::: "memory");
        __syncthreads();
    }

    // ---- epilogue: direct stores (ch/fl/spa folded into agg) ----
    float* ob = out + (size_t)b * COUT * HH * WW;
#pragma unroll
    for (int mt = 0; mt < 4; mt++) {
        const int o = mbase + mt * 16 + (lid >> 2);
#pragma unroll
        for (int nt = 0; nt < 4; nt++) {
            const int nn = nbase + nt * 8 + (lid & 3) * 2;
            const int rp = nn >> 6, px = nn & 63;
            float* dst = ob + ((size_t)o * HH + (y0 + rp)) * WW + px;
            float2 v0 = make_float2(acc[mt][nt][0], acc[mt][nt][1]);
            float2 v1 = make_float2(acc[mt][nt][2], acc[mt][nt][3]);
            *(float2*)(dst) = v0;
            *(float2*)(dst + 8 * (size_t)HH * WW) = v1;
        }
    }
}

// ---------------- launch ----------------------------------------------------
extern "C" void kernel_launch(void* const* d_in, const int* in_sizes, int n_in,
                              void* d_out, int out_size) {
    const float* x        = (const float*)d_in[0];
    const float* weight   = (const float*)d_in[1];
    const float* fc_w     = (const float*)d_in[2];
    const float* bn_gamma = (const float*)d_in[3];
    const float* bn_beta  = (const float*)d_in[4];
    const float* bn_mean  = (const float*)d_in[5];
    const float* bn_var   = (const float*)d_in[6];
    const float* ch_w     = (const float*)d_in[7];
    const float* ch_b     = (const float*)d_in[8];
    const float* flt_w    = (const float*)d_in[9];
    const float* flt_b    = (const float*)d_in[10];
    const float* spa_w    = (const float*)d_in[11];
    const float* spa_b    = (const float*)d_in[12];
    const float* fld_w    = (const float*)d_in[13];
    const float* fld_b    = (const float*)d_in[14];
    const float* ker_w    = (const float*)d_in[15];
    const float* ker_b    = (const float*)d_in[16];
    float* out = (float*)d_out;

    cudaFuncSetAttribute(conv_mma_kernel,
                         cudaFuncAttributeMaxDynamicSharedMemorySize, SM_TOTAL);

    xsplit_pool_kernel<<<BB * 64, 256>>>(x);
    attn_kernel<<<1, 256>>>(fc_w, bn_gamma, bn_beta, bn_mean, bn_var,
                            ch_w, ch_b, flt_w, flt_b, spa_w, spa_b,
                            fld_w, fld_b, ker_w, ker_b);
    agg_kernel<<<dim3(64, 9), 256>>>(weight);
    conv_mma_kernel<<<dim3(32, BB), 256, SM_TOTAL>>>(out);
}

// round 16
// speedup vs baseline: 2.0442x; 1.4433x over previous
#include <cuda_runtime.h>
#include <cuda_fp16.h>
#include <math.h>
#include <stdint.h>

#define BB 16
#define CIN 128
#define COUT 128
#define HH 64
#define WW 64
#define ATT 16
#define KN 4
#define BN_EPS 1e-5f

// ---------------------------------------------------------------------------
// scratch (device globals; no allocation allowed)
// ---------------------------------------------------------------------------
__device__ float g_pooled[BB * CIN];
__device__ float g_coef[BB * KN * 9];
__device__ float g_ch[BB * CIN];
__device__ float g_fl[BB * COUT];
__device__ float g_spa[BB * 9];
// agg filters as fp16 (single plane): layout [b][tap][o(128)][i(128)]
__device__ __align__(128) __half g_a16[(size_t)BB * 9 * 128 * 128];
// x as fp16, channel-pair packed: [b][i2(64)][pix(4096)], u32 = half2(2*i2, 2*i2+1)
__device__ __align__(128) uint32_t g_x16[(size_t)BB * 64 * HH * WW];

// ---------------------------------------------------------------------------
// asm helpers
// ---------------------------------------------------------------------------
__device__ __forceinline__ uint32_t smem_u32(const void* p) {
    uint32_t a;
    asm("{ .reg .u64 t; cvta.to.shared.u64 t, %1; cvt.u32.u64 %0, t; }" : "=r"(a) : "l"(p));
    return a;
}
__device__ __forceinline__ void cp_async16(uint32_t dst, const void* src) {
    asm volatile("cp.async.cg.shared.global [%0], [%1], 16;"
                 :: "r"(dst), "l"(src) : "memory");
}
__device__ __forceinline__ void ldsm_x4(uint32_t* r, uint32_t a) {
    asm volatile("ldmatrix.sync.aligned.m8n8.x4.shared.b16 {%0,%1,%2,%3}, [%4];"
                 : "=r"(r[0]), "=r"(r[1]), "=r"(r[2]), "=r"(r[3]) : "r"(a));
}
__device__ __forceinline__ void ldsm_x2(uint32_t* r, uint32_t a) {
    asm volatile("ldmatrix.sync.aligned.m8n8.x2.shared.b16 {%0,%1}, [%2];"
                 : "=r"(r[0]), "=r"(r[1]) : "r"(a));
}
__device__ __forceinline__ void mma16816_f16(float* c, const uint32_t* a, const uint32_t* b) {
    asm volatile(
        "mma.sync.aligned.m16n8k16.row.col.f32.f16.f16.f32 "
        "{%0,%1,%2,%3}, {%4,%5,%6,%7}, {%8,%9}, {%0,%1,%2,%3};"
        : "+f"(c[0]), "+f"(c[1]), "+f"(c[2]), "+f"(c[3])
        : "r"(a[0]), "r"(a[1]), "r"(a[2]), "r"(a[3]), "r"(b[0]), "r"(b[1]));
}

// ---------------- kernel 1: x -> fp16 pair-packed + global average pool ----
__global__ void __launch_bounds__(256) xsplit_pool_kernel(const float* __restrict__ x) {
    const int bi2 = blockIdx.x;            // b*64 + i2
    const int b = bi2 >> 6;
    const int i2 = bi2 & 63;
    const float* pa = x + ((size_t)(b * CIN + 2 * i2) * HH * WW);
    const float* pb = pa + HH * WW;
    uint4* xo = (uint4*)(g_x16 + (size_t)bi2 * HH * WW);
    float sa = 0.f, sb = 0.f;
    for (int t = threadIdx.x; t < HH * WW / 4; t += 256) {
        float4 va = ((const float4*)pa)[t];
        float4 vb = ((const float4*)pb)[t];
        sa += va.x + va.y + va.z + va.w;
        sb += vb.x + vb.y + vb.z + vb.w;
        uint4 o;
        __half2 h0 = __floats2half2_rn(va.x, vb.x);
        __half2 h1 = __floats2half2_rn(va.y, vb.y);
        __half2 h2 = __floats2half2_rn(va.z, vb.z);
        __half2 h3 = __floats2half2_rn(va.w, vb.w);
        o.x = *(uint32_t*)&h0;
        o.y = *(uint32_t*)&h1;
        o.z = *(uint32_t*)&h2;
        o.w = *(uint32_t*)&h3;
        xo[t] = o;
    }
#pragma unroll
    for (int o2 = 16; o2; o2 >>= 1) {
        sa += __shfl_down_sync(0xffffffff, sa, o2);
        sb += __shfl_down_sync(0xffffffff, sb, o2);
    }
    __shared__ float wsa[8], wsb[8];
    if ((threadIdx.x & 31) == 0) {
        wsa[threadIdx.x >> 5] = sa;
        wsb[threadIdx.x >> 5] = sb;
    }
    __syncthreads();
    if (threadIdx.x == 0) {
        float ta = 0.f, tb = 0.f;
#pragma unroll
        for (int k = 0; k < 8; k++) { ta += wsa[k]; tb += wsb[k]; }
        g_pooled[b * CIN + 2 * i2] = ta * (1.0f / (HH * WW));
        g_pooled[b * CIN + 2 * i2 + 1] = tb * (1.0f / (HH * WW));
    }
}

// ---------------- kernel 2: attention trunk + branches (1 block) -----------
__global__ void attn_kernel(
    const float* __restrict__ fc_w,
    const float* __restrict__ bn_gamma, const float* __restrict__ bn_beta,
    const float* __restrict__ bn_mean, const float* __restrict__ bn_var,
    const float* __restrict__ ch_w, const float* __restrict__ ch_b,
    const float* __restrict__ flt_w, const float* __restrict__ flt_b,
    const float* __restrict__ spa_w, const float* __restrict__ spa_b,
    const float* __restrict__ fld_w, const float* __restrict__ fld_b,
    const float* __restrict__ ker_w, const float* __restrict__ ker_b) {
    __shared__ float sp[BB][CIN];
    __shared__ float sh[BB][ATT];
    __shared__ float sfld[BB][9];
    __shared__ float sker[BB][KN];
    int tid = threadIdx.x;
    for (int t = tid; t < BB * CIN; t += 256) sp[t / CIN][t % CIN] = g_pooled[t];
    __syncthreads();
    {
        int b = tid / ATT, a = tid % ATT;
        float s = 0.f;
#pragma unroll 16
        for (int i = 0; i < CIN; i++) s += sp[b][i] * fc_w[a * CIN + i];
        float inv = rsqrtf(bn_var[a] + BN_EPS);
        s = (s - bn_mean[a]) * (bn_gamma[a] * inv) + bn_beta[a];
        sh[b][a] = fmaxf(s, 0.f);
    }
    __syncthreads();
    for (int t = tid; t < BB * CIN; t += 256) {
        int b = t / CIN, i = t % CIN;
        float s = ch_b[i];
#pragma unroll
        for (int a = 0; a < ATT; a++) s += sh[b][a] * ch_w[i * ATT + a];
        g_ch[t] = 1.f / (1.f + expf(-s));
    }
    for (int t = tid; t < BB * COUT; t += 256) {
        int b = t / COUT, o = t % COUT;
        float s = flt_b[o];
#pragma unroll
        for (int a = 0; a < ATT; a++) s += sh[b][a] * flt_w[o * ATT + a];
        g_fl[t] = 1.f / (1.f + expf(-s));
    }
    for (int t = tid; t < BB * 9; t += 256) {
        int b = t / 9, j = t % 9;
        float s = spa_b[j];
#pragma unroll
        for (int a = 0; a < ATT; a++) s += sh[b][a] * spa_w[j * ATT + a];
        g_spa[t] = 1.f / (1.f + expf(-s));
        float s2 = fld_b[j];
#pragma unroll
        for (int a = 0; a < ATT; a++) s2 += sh[b][a] * fld_w[j * ATT + a];
        sfld[b][j] = 1.f / (1.f + expf(-s2));
    }
    if (tid < BB * KN) {
        int b = tid / KN, n = tid % KN;
        float s = ker_b[n];
#pragma unroll
        for (int a = 0; a < ATT; a++) s += sh[b][a] * ker_w[n * ATT + a];
        sker[b][n] = s;
    }
    __syncthreads();
    if (tid < BB) {
        int b = tid;
        float m = -1e30f;
#pragma unroll
        for (int n = 0; n < KN; n++) m = fmaxf(m, sker[b][n]);
        float e[KN], sum = 0.f;
#pragma unroll
        for (int n = 0; n < KN; n++) { e[n] = expf(sker[b][n] - m); sum += e[n]; }
#pragma unroll
        for (int n = 0; n < KN; n++) sker[b][n] = e[n] / sum;
    }
    __syncthreads();
    for (int t = tid; t < BB * KN * 9; t += 256) {
        int b = t / (KN * 9), n = (t / 9) % KN, j = t % 9;
        g_coef[t] = sker[b][n] * sfld[b][j];
    }
}

// ---------------- kernel 3: aggregation -> fp16 filter tiles ---------------
// grid (64, 9): blockIdx.y owns ONE pq. Single fp16 plane output.
__global__ void __launch_bounds__(256) agg_kernel(const float* __restrict__ weight) {
    __shared__ float scoef[BB * KN * 9];
    __shared__ float sch[BB * CIN];
    __shared__ float sfl[BB * COUT];
    __shared__ float sspa[BB * 9];
    for (int t = threadIdx.x; t < BB * KN * 9; t += 256) scoef[t] = g_coef[t];
    for (int t = threadIdx.x; t < BB * CIN; t += 256) sch[t] = g_ch[t];
    for (int t = threadIdx.x; t < BB * COUT; t += 256) sfl[t] = g_fl[t];
    for (int t = threadIdx.x; t < BB * 9; t += 256) sspa[t] = g_spa[t];
    __syncthreads();
    const int oi = blockIdx.x * 256 + threadIdx.x;   // 0..16383
    const int o = oi >> 7, i = oi & 127;
    const int pq = blockIdx.y;
    const size_t nstride = (size_t)COUT * CIN * 81;
    const float* wbase = weight + (size_t)oi * 81 + pq * 9;
    float w[KN * 9];
#pragma unroll
    for (int n = 0; n < KN; n++)
#pragma unroll
        for (int uv = 0; uv < 9; uv++)
            w[n * 9 + uv] = __ldg(wbase + n * nstride + uv);
#pragma unroll 1
    for (int bg = 0; bg < 4; bg++) {
        const int b0 = bg * 4;
        float acc[4] = {0.f, 0.f, 0.f, 0.f};
#pragma unroll
        for (int k = 0; k < KN * 9; k++) {
            float wv = w[k];
#pragma unroll
            for (int bb = 0; bb < 4; bb++)
                acc[bb] += wv * scoef[(b0 + bb) * (KN * 9) + k];
        }
#pragma unroll
        for (int bb = 0; bb < 4; bb++) {
            int b = b0 + bb;
            float s = acc[bb] * sch[b * CIN + i] * sfl[b * COUT + o] * sspa[b * 9 + pq];
            size_t oidx = (((size_t)b * 9 + pq) * 128 + o) * 128 + i;
            g_a16[oidx] = __float2half_rn(s);
        }
    }
}

// ---------------- kernel 4: double-buffered implicit-GEMM conv (fp16 1-pass)
// R15 structure with single-plane A and B:
//   MMA per chunk: 2 ks x (B frags once; A x4, 16 mma) = 32 mma/warp.
// smem (dynamic 40KB): bufA[j]=j*10240; bufB[j]=20480+j*10240.
#define APITCH 80
#define SM_TOTAL 40960

__global__ void __launch_bounds__(256, 2) conv_mma_kernel(float* __restrict__ out) {
    extern __shared__ __align__(16) char sm[];
    const uint32_t sbase = smem_u32(sm);

    const int tid = threadIdx.x;
    const int wid = tid >> 5;
    const int lid = tid & 31;
    const int b = blockIdx.y;
    const int y0 = blockIdx.x * 2;

    const int mbase = (wid >> 2) * 64;
    const int nbase = (wid & 3) * 32;

    float acc[4][4][4];
#pragma unroll
    for (int mt = 0; mt < 4; mt++)
#pragma unroll
        for (int nt = 0; nt < 4; nt++)
#pragma unroll
            for (int r = 0; r < 4; r++) acc[mt][nt][r] = 0.f;

    const uint32_t* xpb = g_x16 + (size_t)b * 64 * HH * WW;
    const __half* gA = g_a16 + (size_t)b * 9 * 128 * 128;

    // copy-phase thread mappings
    const int bn = tid & 127;
    const int ihalf = tid >> 7;            // 0/1 -> channel offset 0/16 in chunk
    const int brp = bn >> 6;
    const int bpx = bn & 63;
    const int ao = tid >> 1;
    const int au = tid & 1;

    // ldmatrix lane mapping (validated)
    const int r8 = lid & 7;
    const int g1 = (lid >> 3) & 1;
    const int g2 = lid >> 4;
    const uint32_t aoff = (uint32_t)((mbase + g1 * 8 + r8) * APITCH + g2 * 16);
    const uint32_t boff = (uint32_t)((nbase + r8) * APITCH + g1 * 16);

    // ---- A issue for chunk c (cp.async, fire-and-forget): 2x16B/thread ----
    auto issue_a = [&](int c) {
        const int tap = c >> 2, ic0 = (c & 3) * 32;
        const size_t ab = ((size_t)tap * 128 + ao) * 128 + ic0 + au * 16;
        const uint32_t dst = sbase + (uint32_t)((c & 1) * 10240) +
                             (uint32_t)(ao * APITCH + au * 32);
        cp_async16(dst, gA + ab);
        cp_async16(dst + 16, gA + ab + 8);
        asm volatile("cp.async.commit_group;" ::: "memory");
    };
    // ---- B build for chunk c: 8x LDG.32 (pair-packed fp16) + 2x STS.128 ----
    auto build_b = [&](int c) {
        const int tap = c >> 2, ic0 = (c & 3) * 32;
        const int p = tap / 3 - 1, q = tap % 3 - 1;
        const int gy = y0 + brp + p, gx = bpx + q;
        const bool inb = (gx >= 0) && (gx < WW) && (gy >= 0) && (gy < HH);
        const uint32_t* src = xpb + (inb ? (gy * WW + gx) : 0) +
                              (size_t)(ic0 / 2 + ihalf * 8) * (HH * WW);
        uint32_t v[8];
#pragma unroll
        for (int kk = 0; kk < 8; kk++)
            v[kk] = inb ? __ldg(src + (size_t)kk * (HH * WW)) : 0u;
        char* base = sm + 20480 + (c & 1) * 10240 + bn * APITCH + ihalf * 32;
        *(uint4*)(base) = *(const uint4*)(v);
        *(uint4*)(base + 16) = *(const uint4*)(v + 4);
    };

    // prologue: fill buffers for chunk 0
    issue_a(0);
    build_b(0);
    asm volatile("cp.async.wait_group 0;" ::: "memory");
    __syncthreads();

    for (int c = 0; c < 36; c++) {
        // prefetch next chunk into the other buffer (before MMA of this one)
        if (c + 1 < 36) {
            issue_a(c + 1);
            build_b(c + 1);
        }

        // ---- MMA(c): B frags once per ks; A per mt ----
        const uint32_t sA = sbase + (uint32_t)((c & 1) * 10240);
        const uint32_t sB = sbase + 20480u + (uint32_t)((c & 1) * 10240);
#pragma unroll
        for (int ks = 0; ks < 2; ks++) {
            const uint32_t kb = (uint32_t)(ks * 32);
            uint32_t bf[4][2];
#pragma unroll
            for (int nt = 0; nt < 4; nt++)
                ldsm_x2(bf[nt], sB + boff + (uint32_t)(nt * 8 * APITCH) + kb);
#pragma unroll
            for (int mt = 0; mt < 4; mt++) {
                uint32_t af[4];
                ldsm_x4(af, sA + aoff + (uint32_t)(mt * 16 * APITCH) + kb);
#pragma unroll
                for (int nt = 0; nt < 4; nt++) mma16816_f16(acc[mt][nt], af, bf[nt]);
            }
        }
        asm volatile("cp.async.wait_group 0;" ::: "memory");
        __syncthreads();
    }

    // ---- epilogue: direct stores (ch/fl/spa folded into agg) ----
    float* ob = out + (size_t)b * COUT * HH * WW;
#pragma unroll
    for (int mt = 0; mt < 4; mt++) {
        const int o = mbase + mt * 16 + (lid >> 2);
#pragma unroll
        for (int nt = 0; nt < 4; nt++) {
            const int nn = nbase + nt * 8 + (lid & 3) * 2;
            const int rp = nn >> 6, px = nn & 63;
            float* dst = ob + ((size_t)o * HH + (y0 + rp)) * WW + px;
            float2 v0 = make_float2(acc[mt][nt][0], acc[mt][nt][1]);
            float2 v1 = make_float2(acc[mt][nt][2], acc[mt][nt][3]);
            *(float2*)(dst) = v0;
            *(float2*)(dst + 8 * (size_t)HH * WW) = v1;
        }
    }
}

// ---------------- launch ----------------------------------------------------
extern "C" void kernel_launch(void* const* d_in, const int* in_sizes, int n_in,
                              void* d_out, int out_size) {
    const float* x        = (const float*)d_in[0];
    const float* weight   = (const float*)d_in[1];
    const float* fc_w     = (const float*)d_in[2];
    const float* bn_gamma = (const float*)d_in[3];
    const float* bn_beta  = (const float*)d_in[4];
    const float* bn_mean  = (const float*)d_in[5];
    const float* bn_var   = (const float*)d_in[6];
    const float* ch_w     = (const float*)d_in[7];
    const float* ch_b     = (const float*)d_in[8];
    const float* flt_w    = (const float*)d_in[9];
    const float* flt_b    = (const float*)d_in[10];
    const float* spa_w    = (const float*)d_in[11];
    const float* spa_b    = (const float*)d_in[12];
    const float* fld_w    = (const float*)d_in[13];
    const float* fld_b    = (const float*)d_in[14];
    const float* ker_w    = (const float*)d_in[15];
    const float* ker_b    = (const float*)d_in[16];
    float* out = (float*)d_out;

    cudaFuncSetAttribute(conv_mma_kernel,
                         cudaFuncAttributeMaxDynamicSharedMemorySize, SM_TOTAL);

    xsplit_pool_kernel<<<BB * 64, 256>>>(x);
    attn_kernel<<<1, 256>>>(fc_w, bn_gamma, bn_beta, bn_mean, bn_var,
                            ch_w, ch_b, flt_w, flt_b, spa_w, spa_b,
                            fld_w, fld_b, ker_w, ker_b);
    agg_kernel<<<dim3(64, 9), 256>>>(weight);
    conv_mma_kernel<<<dim3(32, BB), 256, SM_TOTAL>>>(out);
}